// round 1
// baseline (speedup 1.0000x reference)
#include <cuda_runtime.h>
#include <math.h>

#define BATCH 512
#define TT    2048
#define INP   32
#define H     256
#define DTC   0.1f
#define EPSC  1e-5f
#define BB    4
#define GRID  (BATCH / BB)   /* 128 blocks */
#define NT    256

__device__ __forceinline__ float sigmoidf_(float v) {
    return 1.0f / (1.0f + expf(-v));
}

// Block-wide reduction of NV per-thread values; results land in stat[0..NV-1].
// 256 threads = 8 warps. Two __syncthreads inside.
template <int NV>
__device__ __forceinline__ void block_reduce(float* vals, float (*red)[8], float* stat) {
    #pragma unroll
    for (int o = 16; o > 0; o >>= 1) {
        #pragma unroll
        for (int i = 0; i < NV; i++)
            vals[i] += __shfl_xor_sync(0xffffffffu, vals[i], o);
    }
    int w = threadIdx.x >> 5, l = threadIdx.x & 31;
    if (l == 0) {
        #pragma unroll
        for (int i = 0; i < NV; i++) red[w][i] = vals[i];
    }
    __syncthreads();
    if (threadIdx.x < NV) {
        float a = 0.f;
        #pragma unroll
        for (int w2 = 0; w2 < 8; w2++) a += red[w2][threadIdx.x];
        stat[threadIdx.x] = a;
    }
    __syncthreads();
}

// acc[r] += sum_k hs[r][k] * W[k*H + j]  (Wcol = W + j). K = H = 256.
// 8-deep weight prefetch per chunk for MLP; hs reads are warp-broadcast LDS.
__device__ __forceinline__ void gemm256(const float* __restrict__ Wcol,
                                        const float* hs, float* acc) {
    #pragma unroll 1
    for (int k = 0; k < H; k += 8) {
        float w[8];
        #pragma unroll
        for (int u = 0; u < 8; u++) w[u] = __ldg(Wcol + (k + u) * H);
        #pragma unroll
        for (int u = 0; u < 8; u++) {
            #pragma unroll
            for (int r = 0; r < BB; r++)
                acc[r] += hs[r * H + k + u] * w[u];
        }
    }
}

// ---------------------------------------------------------------------------
// Kernel 1: precompute ew0[b,t] = mask * sigmoid([x_t, x_{t-1}] @ Wev0 + bev0)
// Written straight into the output buffer (also consumed by the recurrence).
// ---------------------------------------------------------------------------
__global__ void ew0_kernel(const float* __restrict__ x,
                           const float* __restrict__ Wev0,
                           const float* __restrict__ bev0,
                           float* __restrict__ ew0_out) {
    int idx = blockIdx.x * blockDim.x + threadIdx.x;   // = b*T + t
    if (idx >= BATCH * TT) return;
    int t = idx & (TT - 1);
    float r = 0.f;
    if (t > 0) {
        const float* xc = x + (size_t)idx * INP;
        const float* xp = xc - INP;
        float s = bev0[0];
        #pragma unroll
        for (int i = 0; i < INP; i++) s += xc[i] * Wev0[i];
        #pragma unroll
        for (int i = 0; i < INP; i++) s += xp[i] * Wev0[INP + i];
        r = sigmoidf_(s);
    }
    ew0_out[idx] = r;
}

// ---------------------------------------------------------------------------
// Kernel 2: persistent recurrence. Block owns BB batch rows, loops all T steps.
// Thread j owns hidden unit j. Per step, 6 dependent [BB,256]x[256,256] GEMMs.
// ---------------------------------------------------------------------------
__global__ __launch_bounds__(NT) void liquid_kernel(
    const float* __restrict__ x,
    const float* __restrict__ Win0,  const float* __restrict__ bin0,
    const float* __restrict__ Wrec0, const float* __restrict__ brec0,
    const float* __restrict__ Wattn0,const float* __restrict__ battn0,
    const float* __restrict__ tau0,  const float* __restrict__ gamma0, const float* __restrict__ beta0,
    const float* __restrict__ Win1,  const float* __restrict__ bin1,
    const float* __restrict__ Wrec1, const float* __restrict__ brec1,
    const float* __restrict__ Wattn1,const float* __restrict__ battn1,
    const float* __restrict__ Wev1,  const float* __restrict__ bev1,
    const float* __restrict__ tau1,  const float* __restrict__ gamma1, const float* __restrict__ beta1,
    const float* __restrict__ Wskip, const float* __restrict__ bskip,
    const float* __restrict__ Wout,  const float* __restrict__ bout,
    float* __restrict__ out,
    const float* __restrict__ ew0_all,
    float* __restrict__ ew1_all)
{
    __shared__ float h0s[2][BB][H];   // ping-pong layer-0 hidden
    __shared__ float h1s[2][BB][H];   // ping-pong layer-1 hidden
    __shared__ float has0[BB][H];     // h0 * attn0
    __shared__ float has1[BB][H];     // h1 * attn1
    __shared__ float xts[BB][INP];
    __shared__ float red_s[8][8];
    __shared__ float stat_s[8];
    __shared__ float ew1_s[BB];

    const int j    = threadIdx.x;
    const int row0 = blockIdx.x * BB;

    // Per-unit constants in registers
    const float c_bin0   = bin0[j],  c_battn0 = battn0[j], c_brec0 = brec0[j];
    const float it0      = DTC / fminf(fmaxf(tau0[j], 0.1f), 10.0f);
    const float c_g0     = gamma0[j], c_b0 = beta0[j];
    const float c_bin1   = bin1[j],  c_battn1 = battn1[j], c_brec1 = brec1[j];
    const float it1      = DTC / fminf(fmaxf(tau1[j], 0.1f), 10.0f);
    const float c_g1     = gamma1[j], c_b1 = beta1[j], c_bskip = bskip[j];
    const float wv1a     = Wev1[j],  wv1b = Wev1[H + j];
    const float c_bev1   = bev1[0];
    const float c_wout   = Wout[j];

    #pragma unroll
    for (int r = 0; r < BB; r++) { h0s[0][r][j] = 0.f; h1s[0][r][j] = 0.f; }
    __syncthreads();

    for (int t = 0; t < TT; t++) {
        const int cur = t & 1, nxt = cur ^ 1;

        // Stage A: load x_t for this block's rows
        if (j < BB * INP) {
            int r = j >> 5, c = j & 31;
            xts[r][c] = x[((size_t)(row0 + r) * TT + t) * INP + c];
        }
        __syncthreads();   // also orders prev-iter h writes vs this-iter reads

        // Stage B: attn0 = sig(h0@Wattn0), attn1 = sig(h1@Wattn1), inp0 = tanh(x@Win0)
        float a0[BB], a1[BB], i0[BB];
        #pragma unroll
        for (int r = 0; r < BB; r++) { a0[r] = c_battn0; a1[r] = c_battn1; i0[r] = c_bin0; }
        gemm256(Wattn0 + j, &h0s[cur][0][0], a0);
        gemm256(Wattn1 + j, &h1s[cur][0][0], a1);
        #pragma unroll
        for (int k = 0; k < INP; k++) {
            float w = __ldg(Win0 + k * H + j);
            #pragma unroll
            for (int r = 0; r < BB; r++) i0[r] += xts[r][k] * w;
        }
        #pragma unroll
        for (int r = 0; r < BB; r++) {
            i0[r] = tanhf(i0[r]);
            has0[r][j] = h0s[cur][r][j] * sigmoidf_(a0[r]);
            has1[r][j] = h1s[cur][r][j] * sigmoidf_(a1[r]);
        }
        __syncthreads();

        // Stage C: rec0 = tanh((h0*attn0)@Wrec0), rec1 = tanh((h1*attn1)@Wrec1)
        float rc0[BB], rc1[BB];
        #pragma unroll
        for (int r = 0; r < BB; r++) { rc0[r] = c_brec0; rc1[r] = c_brec1; }
        gemm256(Wrec0 + j, &has0[0][0], rc0);
        gemm256(Wrec1 + j, &has1[0][0], rc1);

        // Stage D: layer-0 cell update + LayerNorm
        float v0[BB], sq[8];
        #pragma unroll
        for (int r = 0; r < BB; r++) {
            float e0 = ew0_all[(size_t)(row0 + r) * TT + t];
            float h  = h0s[cur][r][j];
            v0[r] = h + it0 * (-h + i0[r] + tanhf(rc0[r])) * (1.f + e0);
            sq[2 * r] = v0[r]; sq[2 * r + 1] = v0[r] * v0[r];
        }
        block_reduce<8>(sq, red_s, stat_s);
        float h0n[BB], ec[BB];
        #pragma unroll
        for (int r = 0; r < BB; r++) {
            float mu  = stat_s[2 * r] * (1.f / H);
            float var = stat_s[2 * r + 1] * (1.f / H) - mu * mu;
            float hv  = (v0[r] - mu) * rsqrtf(var + EPSC) * c_g0 + c_b0;
            h0n[r] = hv;
            h0s[nxt][r][j] = hv;                       // new h0 (ready after next sync)
            ec[r] = hv * wv1a + h0s[cur][r][j] * wv1b; // ew1 logit contribution (p1 == old h0)
        }
        block_reduce<4>(ec, red_s, stat_s);            // syncs make h0s[nxt] visible
        if (j < BB) {
            float e = (t > 0) ? sigmoidf_(stat_s[j] + c_bev1) : 0.f;
            ew1_s[j] = e;
            ew1_all[(size_t)(row0 + j) * TT + t] = e;
        }
        __syncthreads();

        // Stage E: inp1 = tanh(h0n@Win1), skip = h0n@Wskip + bskip
        float i1[BB], sk[BB];
        #pragma unroll
        for (int r = 0; r < BB; r++) { i1[r] = c_bin1; sk[r] = c_bskip; }
        gemm256(Win1 + j, &h0s[nxt][0][0], i1);
        gemm256(Wskip + j, &h0s[nxt][0][0], sk);

        // Stage F: layer-1 cell update + LayerNorm + skip
        float v1[BB];
        #pragma unroll
        for (int r = 0; r < BB; r++) {
            float h = h1s[cur][r][j];
            v1[r] = h + it1 * (-h + tanhf(i1[r]) + tanhf(rc1[r])) * (1.f + ew1_s[r]);
            sq[2 * r] = v1[r]; sq[2 * r + 1] = v1[r] * v1[r];
        }
        block_reduce<8>(sq, red_s, stat_s);
        #pragma unroll
        for (int r = 0; r < BB; r++) {
            float mu  = stat_s[2 * r] * (1.f / H);
            float var = stat_s[2 * r + 1] * (1.f / H) - mu * mu;
            h1s[nxt][r][j] = (v1[r] - mu) * rsqrtf(var + EPSC) * c_g1 + c_b1 + sk[r];
        }
        // next iteration's Stage-A sync orders these writes
    }

    // Final readout: out[b] = h1 @ Wout + bout
    __syncthreads();
    const int fin = TT & 1;
    float oc[BB];
    #pragma unroll
    for (int r = 0; r < BB; r++) oc[r] = h1s[fin][r][j] * c_wout;
    block_reduce<4>(oc, red_s, stat_s);
    if (j < BB) out[row0 + j] = stat_s[j] + bout[0];
}

extern "C" void kernel_launch(void* const* d_in, const int* in_sizes, int n_in,
                              void* d_out, int out_size) {
    const float* x      = (const float*)d_in[0];
    const float* Win0   = (const float*)d_in[1];
    const float* bin0   = (const float*)d_in[2];
    const float* Wrec0  = (const float*)d_in[3];
    const float* brec0  = (const float*)d_in[4];
    const float* Wattn0 = (const float*)d_in[5];
    const float* battn0 = (const float*)d_in[6];
    const float* Wev0   = (const float*)d_in[7];
    const float* bev0   = (const float*)d_in[8];
    const float* tau0   = (const float*)d_in[9];
    const float* gamma0 = (const float*)d_in[10];
    const float* beta0  = (const float*)d_in[11];
    const float* Win1   = (const float*)d_in[12];
    const float* bin1   = (const float*)d_in[13];
    const float* Wrec1  = (const float*)d_in[14];
    const float* brec1  = (const float*)d_in[15];
    const float* Wattn1 = (const float*)d_in[16];
    const float* battn1 = (const float*)d_in[17];
    const float* Wev1   = (const float*)d_in[18];
    const float* bev1   = (const float*)d_in[19];
    const float* tau1   = (const float*)d_in[20];
    const float* gamma1 = (const float*)d_in[21];
    const float* beta1  = (const float*)d_in[22];
    const float* Wskip  = (const float*)d_in[23];
    const float* bskip  = (const float*)d_in[24];
    const float* Wout   = (const float*)d_in[25];
    const float* bout   = (const float*)d_in[26];

    float* out = (float*)d_out;
    float* ew0 = out + BATCH;                  // [B,T] event weights, layer 0
    float* ew1 = ew0 + (size_t)BATCH * TT;     // [B,T] event weights, layer 1

    ew0_kernel<<<(BATCH * TT + 255) / 256, 256>>>(x, Wev0, bev0, ew0);

    liquid_kernel<<<GRID, NT>>>(
        x, Win0, bin0, Wrec0, brec0, Wattn0, battn0,
        tau0, gamma0, beta0,
        Win1, bin1, Wrec1, brec1, Wattn1, battn1,
        Wev1, bev1, tau1, gamma1, beta1,
        Wskip, bskip, Wout, bout,
        out, ew0, ew1);
}

// round 2
// speedup vs baseline: 2.9247x; 2.9247x over previous
#include <cuda_runtime.h>
#include <math.h>

#define BATCH 512
#define TT    2048
#define INP   32
#define H     256
#define DTC   0.1f
#define EPSC  1e-5f
#define BB    4
#define GRID  (BATCH / BB)   /* 128 blocks */
#define NT    256

__device__ __forceinline__ float sigmoidf_(float v) {
    return 1.0f / (1.0f + expf(-v));
}

// ---- packed f32x2 helpers ------------------------------------------------
__device__ __forceinline__ unsigned long long dup2(float w) {
    unsigned long long d;
    asm("mov.b64 %0, {%1, %1};" : "=l"(d) : "f"(w));
    return d;
}
__device__ __forceinline__ void ffma2(unsigned long long& d,
                                      unsigned long long a,
                                      unsigned long long b) {
    asm("fma.rn.f32x2 %0, %1, %2, %0;" : "+l"(d) : "l"(a), "l"(b));
}
__device__ __forceinline__ float2 unpk(unsigned long long v) {
    float2 r;
    asm("mov.b64 {%0, %1}, %2;" : "=f"(r.x), "=f"(r.y) : "l"(v));
    return r;
}

// Block-wide reduction of NV per-thread values; results in stat[0..NV-1].
template <int NV>
__device__ __forceinline__ void block_reduce(float* vals, float (*red)[16], float* stat) {
    #pragma unroll
    for (int o = 16; o > 0; o >>= 1) {
        #pragma unroll
        for (int i = 0; i < NV; i++)
            vals[i] += __shfl_xor_sync(0xffffffffu, vals[i], o);
    }
    int w = threadIdx.x >> 5, l = threadIdx.x & 31;
    if (l == 0) {
        #pragma unroll
        for (int i = 0; i < NV; i++) red[w][i] = vals[i];
    }
    __syncthreads();
    if (threadIdx.x < NV) {
        float a = 0.f;
        #pragma unroll
        for (int w2 = 0; w2 < 8; w2++) a += red[w2][threadIdx.x];
        stat[threadIdx.x] = a;
    }
    __syncthreads();
}

// Fused pair of [4,256]x[256,256] GEMM columns for unit j.
// h layout: hX[k] = ulonglong2 holding float4(h_row0..h_row3) of unit k.
// Weight loads double-buffered in registers across 8-k chunks.
// SH=true: hB aliases hA (shared activations) -> load once.
template <bool SH>
__device__ __forceinline__ void gemm_pair(
    const float* __restrict__ Wa, const float* __restrict__ Wb, int j,
    const ulonglong2* __restrict__ hA, const ulonglong2* __restrict__ hB,
    unsigned long long* accA, unsigned long long* accB)
{
    float wa[2][8], wb[2][8];
    #pragma unroll
    for (int u = 0; u < 8; u++) {
        wa[0][u] = __ldg(Wa + u * H + j);
        wb[0][u] = __ldg(Wb + u * H + j);
    }
    #pragma unroll 4
    for (int c = 0; c < 32; c++) {
        const int cur = c & 1, nb = cur ^ 1;
        if (c < 31) {
            const float* qa = Wa + (c + 1) * 8 * H + j;
            const float* qb = Wb + (c + 1) * 8 * H + j;
            #pragma unroll
            for (int u = 0; u < 8; u++) {
                wa[nb][u] = __ldg(qa + u * H);
                wb[nb][u] = __ldg(qb + u * H);
            }
        }
        #pragma unroll
        for (int u = 0; u < 8; u++) {
            const int k = c * 8 + u;
            ulonglong2 ha = hA[k];
            unsigned long long w2a = dup2(wa[cur][u]);
            ffma2(accA[0], ha.x, w2a);
            ffma2(accA[1], ha.y, w2a);
            ulonglong2 hb = SH ? ha : hB[k];
            unsigned long long w2b = dup2(wb[cur][u]);
            ffma2(accB[0], hb.x, w2b);
            ffma2(accB[1], hb.y, w2b);
        }
    }
}

// ---------------------------------------------------------------------------
// Kernel 1: ew0[b,t] = mask * sigmoid([x_t, x_{t-1}] @ Wev0 + bev0)
// ---------------------------------------------------------------------------
__global__ void ew0_kernel(const float* __restrict__ x,
                           const float* __restrict__ Wev0,
                           const float* __restrict__ bev0,
                           float* __restrict__ ew0_out) {
    int idx = blockIdx.x * blockDim.x + threadIdx.x;
    if (idx >= BATCH * TT) return;
    int t = idx & (TT - 1);
    float r = 0.f;
    if (t > 0) {
        const float* xc = x + (size_t)idx * INP;
        const float* xp = xc - INP;
        float s = bev0[0];
        #pragma unroll
        for (int i = 0; i < INP; i++) s += xc[i] * Wev0[i];
        #pragma unroll
        for (int i = 0; i < INP; i++) s += xp[i] * Wev0[INP + i];
        r = sigmoidf_(s);
    }
    ew0_out[idx] = r;
}

// ---------------------------------------------------------------------------
// Kernel 2: persistent recurrence, batch-split (4 rows/block).
// ---------------------------------------------------------------------------
__global__ __launch_bounds__(NT, 1) void liquid_kernel(
    const float* __restrict__ x,
    const float* __restrict__ Win0,  const float* __restrict__ bin0,
    const float* __restrict__ Wrec0, const float* __restrict__ brec0,
    const float* __restrict__ Wattn0,const float* __restrict__ battn0,
    const float* __restrict__ tau0,  const float* __restrict__ gamma0, const float* __restrict__ beta0,
    const float* __restrict__ Win1,  const float* __restrict__ bin1,
    const float* __restrict__ Wrec1, const float* __restrict__ brec1,
    const float* __restrict__ Wattn1,const float* __restrict__ battn1,
    const float* __restrict__ Wev1,  const float* __restrict__ bev1,
    const float* __restrict__ tau1,  const float* __restrict__ gamma1, const float* __restrict__ beta1,
    const float* __restrict__ Wskip, const float* __restrict__ bskip,
    const float* __restrict__ Wout,  const float* __restrict__ bout,
    float* __restrict__ out,
    const float* __restrict__ ew0_all,
    float* __restrict__ ew1_all)
{
    // h layout: [unit k][row r] as float4 -> one broadcast LDS.128 per (k).
    __shared__ __align__(16) float h0p[2][H][4];
    __shared__ __align__(16) float h1p[2][H][4];
    __shared__ __align__(16) float ha0p[H][4];
    __shared__ __align__(16) float ha1p[H][4];
    __shared__ __align__(16) float xp[INP][4];
    __shared__ float red_s[8][16];
    __shared__ float stat_s[16];
    __shared__ float ew1_s[BB];

    const int j    = threadIdx.x;
    const int row0 = blockIdx.x * BB;

    const float c_bin0   = bin0[j],  c_battn0 = battn0[j], c_brec0 = brec0[j];
    const float it0      = DTC / fminf(fmaxf(tau0[j], 0.1f), 10.0f);
    const float c_g0     = gamma0[j], c_b0 = beta0[j];
    const float c_bin1   = bin1[j],  c_battn1 = battn1[j], c_brec1 = brec1[j];
    const float it1      = DTC / fminf(fmaxf(tau1[j], 0.1f), 10.0f);
    const float c_g1     = gamma1[j], c_b1 = beta1[j], c_bskip = bskip[j];
    const float wv1a     = Wev1[j],  wv1b = Wev1[H + j];
    const float c_bev1   = bev1[0];
    const float c_wout   = Wout[j];
    const float gw       = c_g0 * wv1a;   // for folded ew1 logit

    // Constants for LN-folded ew1 logit: C2 = sum_j g0_j*wa_j, C3 = sum_j b0_j*wa_j
    {
        float cc[2] = { gw, c_b0 * wv1a };
        block_reduce<2>(cc, red_s, stat_s);
    }
    const float C2 = stat_s[0], C3 = stat_s[1];

    float h0own[BB] = {0.f, 0.f, 0.f, 0.f};
    float h1own[BB] = {0.f, 0.f, 0.f, 0.f};
    *(float4*)&h0p[0][j][0] = make_float4(0.f, 0.f, 0.f, 0.f);
    *(float4*)&h1p[0][j][0] = make_float4(0.f, 0.f, 0.f, 0.f);
    __syncthreads();

    for (int t = 0; t < TT; t++) {
        const int cur = t & 1, nxt = cur ^ 1;

        // ---- Stage A: per-row loads (broadcast) + x_t staging ----
        float e0r[BB];
        #pragma unroll
        for (int r = 0; r < BB; r++)
            e0r[r] = ew0_all[(size_t)(row0 + r) * TT + t];
        if (j < INP) {
            float4 xv;
            xv.x = x[((size_t)(row0 + 0) * TT + t) * INP + j];
            xv.y = x[((size_t)(row0 + 1) * TT + t) * INP + j];
            xv.z = x[((size_t)(row0 + 2) * TT + t) * INP + j];
            xv.w = x[((size_t)(row0 + 3) * TT + t) * INP + j];
            *(float4*)&xp[j][0] = xv;
        }
        __syncthreads();   // also orders prev-iter h1p/h0p writes

        // ---- Stage B: attn0 = sig(h0@Wattn0), attn1 = sig(h1@Wattn1), in0 ----
        unsigned long long aA[2], aB[2];
        aA[0] = aA[1] = dup2(c_battn0);
        aB[0] = aB[1] = dup2(c_battn1);
        gemm_pair<false>(Wattn0, Wattn1, j,
                         (const ulonglong2*)&h0p[cur][0][0],
                         (const ulonglong2*)&h1p[cur][0][0], aA, aB);

        unsigned long long iacc[2];
        iacc[0] = iacc[1] = dup2(c_bin0);
        {
            const ulonglong2* xpp = (const ulonglong2*)&xp[0][0];
            #pragma unroll
            for (int k = 0; k < INP; k++) {
                unsigned long long w2 = dup2(__ldg(Win0 + k * H + j));
                ulonglong2 hx = xpp[k];
                ffma2(iacc[0], hx.x, w2);
                ffma2(iacc[1], hx.y, w2);
            }
        }

        float i0t[BB];
        {
            float2 a0lo = unpk(aA[0]), a0hi = unpk(aA[1]);
            float2 a1lo = unpk(aB[0]), a1hi = unpk(aB[1]);
            float2 i0lo = unpk(iacc[0]), i0hi = unpk(iacc[1]);
            i0t[0] = tanhf(i0lo.x); i0t[1] = tanhf(i0lo.y);
            i0t[2] = tanhf(i0hi.x); i0t[3] = tanhf(i0hi.y);
            *(float4*)&ha0p[j][0] = make_float4(
                h0own[0] * sigmoidf_(a0lo.x), h0own[1] * sigmoidf_(a0lo.y),
                h0own[2] * sigmoidf_(a0hi.x), h0own[3] * sigmoidf_(a0hi.y));
            *(float4*)&ha1p[j][0] = make_float4(
                h1own[0] * sigmoidf_(a1lo.x), h1own[1] * sigmoidf_(a1lo.y),
                h1own[2] * sigmoidf_(a1hi.x), h1own[3] * sigmoidf_(a1hi.y));
        }
        __syncthreads();

        // ---- Stage C: rec0, rec1 ----
        unsigned long long rA[2], rB[2];
        rA[0] = rA[1] = dup2(c_brec0);
        rB[0] = rB[1] = dup2(c_brec1);
        gemm_pair<false>(Wrec0, Wrec1, j,
                         (const ulonglong2*)&ha0p[0][0],
                         (const ulonglong2*)&ha1p[0][0], rA, rB);
        float rc0[BB], rc1[BB];
        {
            float2 lo = unpk(rA[0]), hi = unpk(rA[1]);
            rc0[0] = lo.x; rc0[1] = lo.y; rc0[2] = hi.x; rc0[3] = hi.y;
            lo = unpk(rB[0]); hi = unpk(rB[1]);
            rc1[0] = lo.x; rc1[1] = lo.y; rc1[2] = hi.x; rc1[3] = hi.y;
        }

        // ---- Stage D: layer-0 cell + LN + folded ew1 logit reduction ----
        float v0[BB], vals[16];
        #pragma unroll
        for (int r = 0; r < BB; r++) {
            float h = h0own[r];
            v0[r] = h + it0 * (-h + i0t[r] + tanhf(rc0[r])) * (1.f + e0r[r]);
            vals[4 * r + 0] = v0[r];
            vals[4 * r + 1] = v0[r] * v0[r];
            vals[4 * r + 2] = v0[r] * gw;        // for ew1 logit
            vals[4 * r + 3] = h * wv1b;          // prev-h term of ew1 logit
        }
        block_reduce<16>(vals, red_s, stat_s);

        float h0n[BB];
        #pragma unroll
        for (int r = 0; r < BB; r++) {
            float mu  = stat_s[4 * r] * (1.f / H);
            float var = stat_s[4 * r + 1] * (1.f / H) - mu * mu;
            h0n[r] = (v0[r] - mu) * rsqrtf(var + EPSC) * c_g0 + c_b0;
        }
        *(float4*)&h0p[nxt][j][0] = make_float4(h0n[0], h0n[1], h0n[2], h0n[3]);
        if (j < BB) {
            int r = j;
            float mu  = stat_s[4 * r] * (1.f / H);
            float var = stat_s[4 * r + 1] * (1.f / H) - mu * mu;
            float rs  = rsqrtf(var + EPSC);
            float lg  = rs * (stat_s[4 * r + 2] - mu * C2) + C3 + stat_s[4 * r + 3] + c_bev1;
            float e   = (t > 0) ? sigmoidf_(lg) : 0.f;
            ew1_s[r]  = e;
            ew1_all[(size_t)(row0 + r) * TT + t] = e;
        }
        __syncthreads();   // h0p[nxt] + ew1_s visible

        // ---- Stage E: in1 = h0n@Win1, skip = h0n@Wskip (shared activations) ----
        unsigned long long eA[2], eB[2];
        eA[0] = eA[1] = dup2(c_bin1);
        eB[0] = eB[1] = dup2(c_bskip);
        gemm_pair<true>(Win1, Wskip, j,
                        (const ulonglong2*)&h0p[nxt][0][0],
                        (const ulonglong2*)&h0p[nxt][0][0], eA, eB);
        float i1v[BB], sk[BB];
        {
            float2 lo = unpk(eA[0]), hi = unpk(eA[1]);
            i1v[0] = lo.x; i1v[1] = lo.y; i1v[2] = hi.x; i1v[3] = hi.y;
            lo = unpk(eB[0]); hi = unpk(eB[1]);
            sk[0] = lo.x; sk[1] = lo.y; sk[2] = hi.x; sk[3] = hi.y;
        }

        // ---- Stage F: layer-1 cell + LN + skip ----
        float v1[BB];
        #pragma unroll
        for (int r = 0; r < BB; r++) {
            float h = h1own[r];
            v1[r] = h + it1 * (-h + tanhf(i1v[r]) + tanhf(rc1[r])) * (1.f + ew1_s[r]);
            vals[2 * r]     = v1[r];
            vals[2 * r + 1] = v1[r] * v1[r];
        }
        block_reduce<8>(vals, red_s, stat_s);
        #pragma unroll
        for (int r = 0; r < BB; r++) {
            float mu  = stat_s[2 * r] * (1.f / H);
            float var = stat_s[2 * r + 1] * (1.f / H) - mu * mu;
            h1own[r] = (v1[r] - mu) * rsqrtf(var + EPSC) * c_g1 + c_b1 + sk[r];
            h0own[r] = h0n[r];
        }
        *(float4*)&h1p[nxt][j][0] = make_float4(h1own[0], h1own[1], h1own[2], h1own[3]);
        // next iteration's Stage-A sync orders these writes
    }

    // Final readout: out[b] = h1 @ Wout + bout
    __syncthreads();
    float oc[BB];
    #pragma unroll
    for (int r = 0; r < BB; r++) oc[r] = h1own[r] * c_wout;
    block_reduce<4>(oc, red_s, stat_s);
    if (j < BB) out[row0 + j] = stat_s[j] + bout[0];
}

extern "C" void kernel_launch(void* const* d_in, const int* in_sizes, int n_in,
                              void* d_out, int out_size) {
    const float* x      = (const float*)d_in[0];
    const float* Win0   = (const float*)d_in[1];
    const float* bin0   = (const float*)d_in[2];
    const float* Wrec0  = (const float*)d_in[3];
    const float* brec0  = (const float*)d_in[4];
    const float* Wattn0 = (const float*)d_in[5];
    const float* battn0 = (const float*)d_in[6];
    const float* Wev0   = (const float*)d_in[7];
    const float* bev0   = (const float*)d_in[8];
    const float* tau0   = (const float*)d_in[9];
    const float* gamma0 = (const float*)d_in[10];
    const float* beta0  = (const float*)d_in[11];
    const float* Win1   = (const float*)d_in[12];
    const float* bin1   = (const float*)d_in[13];
    const float* Wrec1  = (const float*)d_in[14];
    const float* brec1  = (const float*)d_in[15];
    const float* Wattn1 = (const float*)d_in[16];
    const float* battn1 = (const float*)d_in[17];
    const float* Wev1   = (const float*)d_in[18];
    const float* bev1   = (const float*)d_in[19];
    const float* tau1   = (const float*)d_in[20];
    const float* gamma1 = (const float*)d_in[21];
    const float* beta1  = (const float*)d_in[22];
    const float* Wskip  = (const float*)d_in[23];
    const float* bskip  = (const float*)d_in[24];
    const float* Wout   = (const float*)d_in[25];
    const float* bout   = (const float*)d_in[26];

    float* out = (float*)d_out;
    float* ew0 = out + BATCH;
    float* ew1 = ew0 + (size_t)BATCH * TT;

    ew0_kernel<<<(BATCH * TT + 255) / 256, 256>>>(x, Wev0, bev0, ew0);

    liquid_kernel<<<GRID, NT>>>(
        x, Win0, bin0, Wrec0, brec0, Wattn0, battn0,
        tau0, gamma0, beta0,
        Win1, bin1, Wrec1, brec1, Wattn1, battn1,
        Wev1, bev1, tau1, gamma1, beta1,
        Wskip, bskip, Wout, bout,
        out, ew0, ew1);
}